// round 3
// baseline (speedup 1.0000x reference)
#include <cuda_runtime.h>

#define BB    64
#define CC    256
#define DDIM  256
#define HW    784
#define ATTRN 300
#define O1    32

// scratch (device globals — no allocation allowed)
__device__ float g_emb[BB * CC];           // s1-scaled embedding
__device__ float g_CM[BB * O1 * DDIM];     // per-batch folded conv1 x circulant

// ---- packed f32x2 helpers -------------------------------------------------
__device__ __forceinline__ unsigned long long fma2(unsigned long long a,
                                                   unsigned long long b,
                                                   unsigned long long c) {
    unsigned long long d;
    asm("fma.rn.f32x2 %0, %1, %2, %3;" : "=l"(d) : "l"(a), "l"(b), "l"(c));
    return d;
}
__device__ __forceinline__ float2 unpk2(unsigned long long v) {
    float2 r;
    asm("mov.b64 {%0, %1}, %2;" : "=f"(r.x), "=f"(r.y) : "l"(v));
    return r;
}

// ---------------------------------------------------------------------------
// Kernel 1: g_emb[b,c] = s1[c] * (W_emb[c]·attr[b] + b_emb[c])
// All of attr (64x300) staged in shared; warp per channel, W row in registers,
// 64-batch loop fed entirely from shared (no global latency in the loop).
// grid = 32 blocks x 256 threads; warp w handles channel blockIdx*8+w.
// ---------------------------------------------------------------------------
#define K1_SH (BB * ATTRN + 32)   // +32 zero pad for branchless tail
__global__ void __launch_bounds__(256) k1_emb(
    const float* __restrict__ attr_oh,   // [B, ATTR]
    const float* __restrict__ W_emb,     // [C, ATTR]
    const float* __restrict__ b_emb,     // [C]
    const float* __restrict__ s1)        // [C]
{
    extern __shared__ float sh[];        // attr, padded
    int tid = threadIdx.x;
    for (int i = tid; i < BB * ATTRN; i += 256) sh[i] = attr_oh[i];
    for (int i = BB * ATTRN + tid; i < K1_SH; i += 256) sh[i] = 0.f;

    int w = tid >> 5, l = tid & 31;
    int c = blockIdx.x * 8 + w;

    float wreg[10];
#pragma unroll
    for (int i = 0; i < 10; i++) {
        int a = l + 32 * i;
        wreg[i] = (a < ATTRN) ? W_emb[c * ATTRN + a] : 0.f;
    }
    float s1c = s1[c], bec = b_emb[c];
    __syncthreads();

#pragma unroll 2
    for (int b = 0; b < BB; b++) {
        const float* at = sh + b * ATTRN;
        float acc = 0.f;
#pragma unroll
        for (int i = 0; i < 10; i++) acc = fmaf(wreg[i], at[l + 32 * i], acc);
#pragma unroll
        for (int off = 16; off; off >>= 1) acc += __shfl_xor_sync(0xffffffffu, acc, off);
        if (l == 0) g_emb[b * CC + c] = s1c * (acc + bec);
    }
}

// ---------------------------------------------------------------------------
// Kernel 2: CM[b,o,m] = sum_j conv1_w[o,(m+j)&255] * sa[b,j]
// Sketch sa built in-block by shared atomics (h1 gather). conv1_w stored
// DUPLICATED as float2 so FFMA2 multiplier comes straight from LDS.64.
// Batch pairs packed into the f32x2 lanes. 4 batches per block.
// grid = (8 m-tiles, 16 batch-groups), 256 threads, ~70KB dyn smem
// ---------------------------------------------------------------------------
__global__ void __launch_bounds__(256) k2_cm(
    const float* __restrict__ conv1_w,   // [32,256]
    const int*   __restrict__ h1)        // [256]
{
    extern __shared__ char sm2[];
    float2* wdup = (float2*)sm2;                    // [32*256] dup, 64KB
    float2* sasp = (float2*)(sm2 + O1 * DDIM * 8);  // [2*256] batch-pair sketches
    int tid = threadIdx.x;
    int b0 = blockIdx.y * 4;

    for (int i = tid; i < O1 * DDIM; i += 256) {
        float v = conv1_w[i];
        wdup[i] = make_float2(v, v);
    }
    for (int i = tid; i < 2 * DDIM; i += 256) sasp[i] = make_float2(0.f, 0.f);
    __syncthreads();

    int hv = h1[tid];
#pragma unroll
    for (int p = 0; p < 2; p++) {
        float vx = g_emb[(b0 + 2 * p) * CC + tid];
        float vy = g_emb[(b0 + 2 * p + 1) * CC + tid];
        atomicAdd(&sasp[p * DDIM + hv].x, vx);
        atomicAdd(&sasp[p * DDIM + hv].y, vy);
    }
    __syncthreads();

    int m  = blockIdx.x * 32 + (tid & 31);
    int o0 = (tid >> 5) << 2;
    const unsigned long long* wd = (const unsigned long long*)wdup;
    const unsigned long long* sp = (const unsigned long long*)sasp;

    unsigned long long acc[2][4];
#pragma unroll
    for (int p = 0; p < 2; p++)
#pragma unroll
        for (int oo = 0; oo < 4; oo++) acc[p][oo] = 0ull;

#pragma unroll 4
    for (int j = 0; j < DDIM; j++) {
        int idx = (m + j) & (DDIM - 1);
        unsigned long long s0 = sp[j], s1v = sp[DDIM + j];
#pragma unroll
        for (int oo = 0; oo < 4; oo++) {
            unsigned long long wv = wd[(o0 + oo) * DDIM + idx];
            acc[0][oo] = fma2(wv, s0,  acc[0][oo]);
            acc[1][oo] = fma2(wv, s1v, acc[1][oo]);
        }
    }

#pragma unroll
    for (int p = 0; p < 2; p++)
#pragma unroll
        for (int oo = 0; oo < 4; oo++) {
            float2 f = unpk2(acc[p][oo]);
            g_CM[((b0 + 2 * p)     * O1 + o0 + oo) * DDIM + m] = f.x;
            g_CM[((b0 + 2 * p + 1) * O1 + o0 + oo) * DDIM + m] = f.y;
        }
}

// ---------------------------------------------------------------------------
// Kernel 3: fused GEMM (FFMA2) + sigmoid gate + broadcast multiply
// A stored as duplicated c-pairs {a_c,a_c,a_c+1,a_c+1} -> 1 LDS.128 feeds
// 4 FFMA2. grid = (7 tiles, 64 batches), 224 threads, ~70KB dyn smem
// ---------------------------------------------------------------------------
#define PAD4 129   // float4 row stride for A
__global__ void __launch_bounds__(224) k3_main(
    const float* __restrict__ x,        // [B, C, HW]
    const int*   __restrict__ h2,
    const float* __restrict__ s2,
    const float* __restrict__ conv2_w,  // [32]
    float* __restrict__ out_map,        // [B, HW]
    float* __restrict__ out_feat)       // [B, C, HW]
{
    extern __shared__ char sm3[];
    float4* A4    = (float4*)sm3;                          // [32*PAD4]
    float4* red4  = (float4*)(sm3 + O1 * PAD4 * 16);       // [224]
    float4* marr4 = (float4*)((char*)red4 + 224 * 16);     // [28]
    float*  w2s   = (float*)((char*)marr4 + 28 * 16);      // [32]

    int b    = blockIdx.y;
    int tile = blockIdx.x;
    int tid  = threadIdx.x;
    int og   = tid & 7;        // o-group (4 channels)
    int ql   = tid >> 3;       // quad 0..27

    const float* cmb = g_CM + b * O1 * DDIM;
    for (int i = tid; i < O1 * CC; i += 224) {
        int o = i >> 8, c = i & 255;
        float v = s2[c] * cmb[(o << 8) + h2[c]];
        float* dst = (float*)&A4[o * PAD4 + (c >> 1)];
        dst[(c & 1) * 2 + 0] = v;
        dst[(c & 1) * 2 + 1] = v;
    }
    if (tid < O1) w2s[tid] = conv2_w[tid];
    __syncthreads();

    int p = (tile * 28 + ql) * 4;      // 196 quads exactly
    const float* xb = x + (size_t)b * CC * HW;

    unsigned long long acc2[4][2];
#pragma unroll
    for (int oo = 0; oo < 4; oo++) { acc2[oo][0] = 0ull; acc2[oo][1] = 0ull; }

    const float4* Ab = A4 + (og * 4) * PAD4;
#pragma unroll 2
    for (int c2 = 0; c2 < CC / 2; c2++) {
        ulonglong2 xv0 = *(const ulonglong2*)(xb + (size_t)(2 * c2)     * HW + p);
        ulonglong2 xv1 = *(const ulonglong2*)(xb + (size_t)(2 * c2 + 1) * HW + p);
#pragma unroll
        for (int oo = 0; oo < 4; oo++) {
            ulonglong2 ap = *(const ulonglong2*)&Ab[oo * PAD4 + c2]; // {dup(a_c), dup(a_c1)}
            acc2[oo][0] = fma2(ap.x, xv0.x, acc2[oo][0]);
            acc2[oo][1] = fma2(ap.x, xv0.y, acc2[oo][1]);
            acc2[oo][0] = fma2(ap.y, xv1.x, acc2[oo][0]);
            acc2[oo][1] = fma2(ap.y, xv1.y, acc2[oo][1]);
        }
    }

    // relu + conv2 partial over this thread's 4 o's
    float4 ps = make_float4(0.f, 0.f, 0.f, 0.f);
#pragma unroll
    for (int oo = 0; oo < 4; oo++) {
        float w = w2s[og * 4 + oo];
        float2 lo = unpk2(acc2[oo][0]);
        float2 hi = unpk2(acc2[oo][1]);
        ps.x = fmaf(w, fmaxf(lo.x, 0.f), ps.x);
        ps.y = fmaf(w, fmaxf(lo.y, 0.f), ps.y);
        ps.z = fmaf(w, fmaxf(hi.x, 0.f), ps.z);
        ps.w = fmaf(w, fmaxf(hi.y, 0.f), ps.w);
    }
    red4[tid] = ps;
    __syncthreads();

    if (tid < 28) {
        float4 t = make_float4(0.f, 0.f, 0.f, 0.f);
#pragma unroll
        for (int g = 0; g < 8; g++) {
            float4 r = red4[tid * 8 + g];
            t.x += r.x; t.y += r.y; t.z += r.z; t.w += r.w;
        }
        float4 mm;
        mm.x = 1.f / (1.f + __expf(-t.x));
        mm.y = 1.f / (1.f + __expf(-t.y));
        mm.z = 1.f / (1.f + __expf(-t.z));
        mm.w = 1.f / (1.f + __expf(-t.w));
        marr4[tid] = mm;
        *(float4*)(out_map + b * HW + (tile * 28 + tid) * 4) = mm;
    }
    __syncthreads();

    // epilogue: feat = map * x (x re-read hits L1/L2)
    float* fb = out_feat + (size_t)b * CC * HW;
    for (int i = tid; i < CC * 28; i += 224) {
        int c  = i / 28;
        int qq = i - c * 28;
        int pp = (tile * 28 + qq) * 4;
        float4 xv = *(const float4*)(xb + (size_t)c * HW + pp);
        float4 mm = marr4[qq];
        float4 r;
        r.x = mm.x * xv.x; r.y = mm.y * xv.y;
        r.z = mm.z * xv.z; r.w = mm.w * xv.w;
        *(float4*)(fb + (size_t)c * HW + pp) = r;
    }
}

// ---------------------------------------------------------------------------
extern "C" void kernel_launch(void* const* d_in, const int* in_sizes, int n_in,
                              void* d_out, int out_size)
{
    (void)in_sizes; (void)n_in; (void)out_size;
    const float* x        = (const float*)d_in[0];
    const float* attr_oh  = (const float*)d_in[1];
    const float* W_emb    = (const float*)d_in[2];
    const float* b_emb    = (const float*)d_in[3];
    const int*   h1       = (const int*)  d_in[4];
    const float* s1       = (const float*)d_in[5];
    const int*   h2       = (const int*)  d_in[6];
    const float* s2       = (const float*)d_in[7];
    const float* conv1_w  = (const float*)d_in[8];
    const float* conv2_w  = (const float*)d_in[9];

    float* out      = (float*)d_out;
    float* out_map  = out;               // [64,784]
    float* out_feat = out + BB * HW;     // [64,256,784]

    const int sh1 = K1_SH * 4;                               // ~77 KB
    const int sh2 = O1 * DDIM * 8 + 2 * DDIM * 8;            // ~68 KB
    const int sh3 = O1 * PAD4 * 16 + 224 * 16 + 28 * 16 + O1 * 4;  // ~70 KB
    cudaFuncSetAttribute(k1_emb,  cudaFuncAttributeMaxDynamicSharedMemorySize, sh1);
    cudaFuncSetAttribute(k2_cm,   cudaFuncAttributeMaxDynamicSharedMemorySize, sh2);
    cudaFuncSetAttribute(k3_main, cudaFuncAttributeMaxDynamicSharedMemorySize, sh3);

    k1_emb<<<32, 256, sh1>>>(attr_oh, W_emb, b_emb, s1);
    k2_cm<<<dim3(8, 16), 256, sh2>>>(conv1_w, h1);
    k3_main<<<dim3(7, BB), 224, sh3>>>(x, h2, s2, conv2_w, out_map, out_feat);
}